// round 14
// baseline (speedup 1.0000x reference)
#include <cuda_runtime.h>
#include <cuda_bf16.h>
#include <math.h>

// ---------------------------------------------------------------------------
// CrystalGraphAttention  (B=8, N=1024, D=256, H=8, dk=dv=64)
//
// All GEMMs: warp-mma m16n8k16 bf16 3-term hi/lo split.
// R14: ALL scattered in-loop LDGs moved to batched smem staging:
//   qkv/oproj : A-tile staged pre-split (stride-20, conflict-free LDS)
//   attn      : edge-mask tile staged as packed bf16 (stride-36, conflict-free)
// ---------------------------------------------------------------------------

#define NEGBIG (-1.0e9f)

static __device__ float g_q [8 * 8 * 1024 * 64];    // [B,H,N,64]
static __device__ float g_k [8 * 8 * 1024 * 64];
static __device__ float g_v [8 * 8 * 1024 * 64];
static __device__ float g_ctx[8 * 1024 * 512];      // [B*N, H*64]

// ---------------------------------------------------------------------------
#define MMA_BF16(c, a, b0, b1)                                              \
    asm volatile(                                                           \
        "mma.sync.aligned.m16n8k16.row.col.f32.bf16.bf16.f32 "              \
        "{%0,%1,%2,%3}, {%4,%5,%6,%7}, {%8,%9}, {%0,%1,%2,%3};"             \
        : "+f"((c)[0]), "+f"((c)[1]), "+f"((c)[2]), "+f"((c)[3])            \
        : "r"((a)[0]), "r"((a)[1]), "r"((a)[2]), "r"((a)[3]),               \
          "r"(b0), "r"(b1))

__device__ __forceinline__ unsigned pack_bf2(float x, float y)
{
    unsigned r;
    asm("cvt.rn.bf16x2.f32 %0, %1, %2;" : "=r"(r) : "f"(y), "f"(x));
    return r;
}

__device__ __forceinline__ float bf16_hi_f(float x)
{
    return __bfloat162float(__float2bfloat16(x));
}

// split a float4 (two adjacent pairs) into hi/lo packed uints
__device__ __forceinline__ void split4(float4 v, unsigned& h0, unsigned& h1,
                                       unsigned& l0, unsigned& l1)
{
    float a = bf16_hi_f(v.x), b = bf16_hi_f(v.y);
    float c = bf16_hi_f(v.z), d = bf16_hi_f(v.w);
    h0 = pack_bf2(a, b);          h1 = pack_bf2(c, d);
    l0 = pack_bf2(v.x - a, v.y - b);
    l1 = pack_bf2(v.z - c, v.w - d);
}

// ---------------------------------------------------------------------------
// Kernel 1: QKV projection.  A staged pre-split in smem (NEW).
// grid = (64 mtiles, 8 heads, 3 weights), block = 256 (8 warps).
// As stride 20 uints: A-frag read banks = 20*g + 8*kc + tg -> all 32 distinct.
// ---------------------------------------------------------------------------
__global__ __launch_bounds__(256, 2) void qkv_kernel(
    const float* __restrict__ X,
    const float* __restrict__ Wq,
    const float* __restrict__ Wk,
    const float* __restrict__ Wv)
{
    __shared__ __align__(16) unsigned Ahi[128 * 20];   // 10 KB
    __shared__ __align__(16) unsigned Alo[128 * 20];   // 10 KB
    __shared__ __align__(16) unsigned Whi[16 * 72];    // 4.5 KB
    __shared__ __align__(16) unsigned Wlo[16 * 72];    // 4.5 KB

    const int tid  = threadIdx.x;
    const int wid  = tid >> 5;
    const int lane = tid & 31;
    const int g    = lane >> 2;
    const int tg   = lane & 3;
    const int mt = blockIdx.x, h = blockIdx.y, w = blockIdx.z;
    const float* W = (w == 0) ? Wq : (w == 1) ? Wk : Wv;
    float* Out     = (w == 0) ? g_q : (w == 1) ? g_k : g_v;

    const int ar = tid >> 1;              // A staging row (0..127)
    const int ac = (tid & 1) * 16;        // A staging col base (0 / 16)
    const int kp = tid >> 4;              // W staging k-pair (0..15)
    const int n4 = (tid & 15) * 4;        // W staging n base

    const int arow = wid * 16 + g;        // A-frag row (this warp)

    float C[8][4];
    #pragma unroll
    for (int nt = 0; nt < 8; nt++)
        #pragma unroll
        for (int j = 0; j < 4; j++) C[nt][j] = 0.f;

    for (int k0 = 0; k0 < 256; k0 += 32) {
        __syncthreads();
        // ---- stage A chunk [128 x 32], split hi/lo ----
        {
            const float* asrc = &X[(size_t)(mt * 128 + ar) * 256 + k0 + ac];
            float4 v0 = *(const float4*)&asrc[0];
            float4 v1 = *(const float4*)&asrc[4];
            float4 v2 = *(const float4*)&asrc[8];
            float4 v3 = *(const float4*)&asrc[12];
            uint4 h4a, l4a, h4b, l4b;
            split4(v0, h4a.x, h4a.y, l4a.x, l4a.y);
            split4(v1, h4a.z, h4a.w, l4a.z, l4a.w);
            split4(v2, h4b.x, h4b.y, l4b.x, l4b.y);
            split4(v3, h4b.z, h4b.w, l4b.z, l4b.w);
            *(uint4*)&Ahi[ar * 20 + ac / 2]     = h4a;
            *(uint4*)&Ahi[ar * 20 + ac / 2 + 4] = h4b;
            *(uint4*)&Alo[ar * 20 + ac / 2]     = l4a;
            *(uint4*)&Alo[ar * 20 + ac / 2 + 4] = l4b;
        }
        // ---- stage W chunk [32 x 64], split hi/lo ----
        {
            const float* wr0 = &W[(size_t)(k0 + 2 * kp) * 512 + h * 64 + n4];
            const float* wr1 = wr0 + 512;
            float4 w0 = *(const float4*)wr0;
            float4 w1 = *(const float4*)wr1;
            float h0x = bf16_hi_f(w0.x), h1x = bf16_hi_f(w1.x);
            float h0y = bf16_hi_f(w0.y), h1y = bf16_hi_f(w1.y);
            float h0z = bf16_hi_f(w0.z), h1z = bf16_hi_f(w1.z);
            float h0w = bf16_hi_f(w0.w), h1w = bf16_hi_f(w1.w);
            uint4 hi4, lo4;
            hi4.x = pack_bf2(h0x, h1x);
            hi4.y = pack_bf2(h0y, h1y);
            hi4.z = pack_bf2(h0z, h1z);
            hi4.w = pack_bf2(h0w, h1w);
            lo4.x = pack_bf2(w0.x - h0x, w1.x - h1x);
            lo4.y = pack_bf2(w0.y - h0y, w1.y - h1y);
            lo4.z = pack_bf2(w0.z - h0z, w1.z - h1z);
            lo4.w = pack_bf2(w0.w - h0w, w1.w - h1w);
            *(uint4*)&Whi[kp * 72 + n4] = hi4;
            *(uint4*)&Wlo[kp * 72 + n4] = lo4;
        }
        __syncthreads();

        #pragma unroll
        for (int kc = 0; kc < 2; kc++) {
            unsigned ahi[4], alo[4];
            {
                int c0 = kc * 8 + tg;
                ahi[0] = Ahi[arow * 20 + c0];
                ahi[1] = Ahi[(arow + 8) * 20 + c0];
                ahi[2] = Ahi[arow * 20 + c0 + 4];
                ahi[3] = Ahi[(arow + 8) * 20 + c0 + 4];
                alo[0] = Alo[arow * 20 + c0];
                alo[1] = Alo[(arow + 8) * 20 + c0];
                alo[2] = Alo[arow * 20 + c0 + 4];
                alo[3] = Alo[(arow + 8) * 20 + c0 + 4];
            }
            #pragma unroll
            for (int nt = 0; nt < 8; nt++) {
                int base = (kc * 8 + tg) * 72 + nt * 8 + g;
                unsigned b0h = Whi[base], b1h = Whi[base + 4 * 72];
                unsigned b0l = Wlo[base], b1l = Wlo[base + 4 * 72];
                MMA_BF16(C[nt], ahi, b0h, b1h);
                MMA_BF16(C[nt], ahi, b0l, b1l);
                MMA_BF16(C[nt], alo, b0h, b1h);
            }
        }
    }

    #pragma unroll
    for (int nt = 0; nt < 8; nt++) {
        int m0 = mt * 128 + wid * 16 + g;
        int m1 = m0 + 8;
        int b0i = m0 >> 10, s0 = m0 & 1023;
        int b1i = m1 >> 10, s1 = m1 & 1023;
        float2 r0, r1;
        r0.x = C[nt][0]; r0.y = C[nt][1];
        r1.x = C[nt][2]; r1.y = C[nt][3];
        *(float2*)&Out[(size_t)((b0i * 8 + h) * 1024 + s0) * 64 + nt * 8 + 2 * tg] = r0;
        *(float2*)&Out[(size_t)((b1i * 8 + h) * 1024 + s1) * 64 + nt * 8 + 2 * tg] = r1;
    }
}

// ---------------------------------------------------------------------------
// Kernel 2: flash attention, bf16 3-term, NO-MAX softmax.
// R12 tiles + NEW: edge-mask tile staged in smem (packed bf16, stride 36
// -> exp-phase read banks 4g+tg, all 32 distinct).  Dynamic smem 56 KB.
// grid = (8 qtiles, 8 heads, 8 batches), block = 256 (8 warps).
// ---------------------------------------------------------------------------
#define A_KHI 0
#define A_KLO 2304
#define A_VHI 4608
#define A_VLO 7168
#define A_MB  9728
#define ATTN_SMEM_UINTS 14336
#define ATTN_SMEM_BYTES (ATTN_SMEM_UINTS * 4)

__global__ __launch_bounds__(256, 2) void attn_kernel(
    const float* __restrict__ em,     // [B,1,N,N]
    const float* __restrict__ dw)     // [B,N]
{
    extern __shared__ __align__(16) unsigned sm[];
    unsigned* KsHi = sm + A_KHI;      // [key][dpair]  stride 36
    unsigned* KsLo = sm + A_KLO;
    unsigned* VtHi = sm + A_VHI;      // [d][keypair]  stride 40
    unsigned* VtLo = sm + A_VLO;
    unsigned* Mb   = sm + A_MB;       // [qrow][keypair] stride 36

    const int tid  = threadIdx.x;
    const int wid  = tid >> 5;
    const int lane = tid & 31;
    const int g    = lane >> 2;
    const int tg   = lane & 3;
    const int qt = blockIdx.x, h = blockIdx.y, b = blockIdx.z;
    const int qrow0 = qt * 128 + wid * 16;

    const float* qb = &g_q[(size_t)((b * 8 + h) * 1024 + qrow0) * 64];
    const float* kb = &g_k[(size_t)(b * 8 + h) * 1024 * 64];
    const float* vb = &g_v[(size_t)(b * 8 + h) * 1024 * 64];
    const float* emb = em + (size_t)b * 1024 * 1024;
    const float* dwb = dw + b * 1024;

    // ---- Q fragments (scaled 1/8), packed bf16x2 hi/lo, resident ----
    unsigned qhi[4][4], qlo[4][4];
    #pragma unroll
    for (int kc = 0; kc < 4; kc++) {
        #pragma unroll
        for (int j = 0; j < 4; j++) {
            int row = (j & 1) ? g + 8 : g;
            int col = kc * 16 + 2 * tg + ((j >> 1) ? 8 : 0);
            float2 qv = *(const float2*)&qb[(size_t)row * 64 + col];
            qv.x *= 0.125f; qv.y *= 0.125f;
            float hx = bf16_hi_f(qv.x), hy = bf16_hi_f(qv.y);
            qhi[kc][j] = pack_bf2(hx, hy);
            qlo[kc][j] = pack_bf2(qv.x - hx, qv.y - hy);
        }
    }

    float O[8][4];
    #pragma unroll
    for (int nt = 0; nt < 8; nt++)
        #pragma unroll
        for (int j = 0; j < 4; j++) O[nt][j] = 0.f;
    float li0 = 0.f, li1 = 0.f;

    // staging maps
    const int kr  = tid >> 4;            // K: key row base (0..15)
    const int kc4 = (tid & 15) * 4;      // K: d base
    const int vkp = tid & 31;            // V: keypair (0..31)
    const int vd0 = (tid >> 5) * 8;      // V: d group base
    const int mr  = tid >> 1;            // Mask: row (0..127)
    const int mh  = (tid & 1) * 32;      // Mask: key half base

    for (int kt = 0; kt < 16; kt++) {
        __syncthreads();
        // ---- stage K (hi/lo, [key][dpair] stride 36) ----
        {
            int r = kr;
            #pragma unroll
            for (int t = 0; t < 4; t++, r += 16) {
                float4 kv = *(const float4*)&kb[(size_t)(kt * 64 + r) * 64 + kc4];
                float h0 = bf16_hi_f(kv.x), h1 = bf16_hi_f(kv.y);
                float h2 = bf16_hi_f(kv.z), h3 = bf16_hi_f(kv.w);
                uint2 hp, lp;
                hp.x = pack_bf2(h0, h1);          hp.y = pack_bf2(h2, h3);
                lp.x = pack_bf2(kv.x - h0, kv.y - h1);
                lp.y = pack_bf2(kv.z - h2, kv.w - h3);
                *(uint2*)&KsHi[r * 36 + kc4 / 2] = hp;
                *(uint2*)&KsLo[r * 36 + kc4 / 2] = lp;
            }
        }
        // ---- stage V transposed (hi/lo, [d][keypair] stride 40) ----
        {
            const float* vr0 = &vb[(size_t)(kt * 64 + 2 * vkp) * 64 + vd0];
            const float* vr1 = vr0 + 64;
            float e0[8], e1[8];
            float4 t0 = *(const float4*)&vr0[0];
            float4 t1 = *(const float4*)&vr0[4];
            float4 u0 = *(const float4*)&vr1[0];
            float4 u1 = *(const float4*)&vr1[4];
            e0[0]=t0.x; e0[1]=t0.y; e0[2]=t0.z; e0[3]=t0.w;
            e0[4]=t1.x; e0[5]=t1.y; e0[6]=t1.z; e0[7]=t1.w;
            e1[0]=u0.x; e1[1]=u0.y; e1[2]=u0.z; e1[3]=u0.w;
            e1[4]=u1.x; e1[5]=u1.y; e1[6]=u1.z; e1[7]=u1.w;
            #pragma unroll
            for (int i = 0; i < 8; i++) {
                float h0 = bf16_hi_f(e0[i]), h1 = bf16_hi_f(e1[i]);
                VtHi[(vd0 + i) * 40 + vkp] = pack_bf2(h0, h1);
                VtLo[(vd0 + i) * 40 + vkp] = pack_bf2(e0[i] - h0, e1[i] - h1);
            }
        }
        // ---- stage mask tile [128 x 64] as packed bf16 pairs ----
        {
            const float* msrc = emb + (size_t)(qt * 128 + mr) * 1024 + kt * 64 + mh;
            uint4 p0, p1;
            float4 v0 = *(const float4*)&msrc[0];
            float4 v1 = *(const float4*)&msrc[4];
            float4 v2 = *(const float4*)&msrc[8];
            float4 v3 = *(const float4*)&msrc[12];
            p0.x = pack_bf2(v0.x, v0.y); p0.y = pack_bf2(v0.z, v0.w);
            p0.z = pack_bf2(v1.x, v1.y); p0.w = pack_bf2(v1.z, v1.w);
            p1.x = pack_bf2(v2.x, v2.y); p1.y = pack_bf2(v2.z, v2.w);
            p1.z = pack_bf2(v3.x, v3.y); p1.w = pack_bf2(v3.z, v3.w);
            *(uint4*)&Mb[mr * 36 + mh / 2]     = p0;
            *(uint4*)&Mb[mr * 36 + mh / 2 + 4] = p1;
            float4 v4 = *(const float4*)&msrc[16];
            float4 v5 = *(const float4*)&msrc[20];
            float4 v6 = *(const float4*)&msrc[24];
            float4 v7 = *(const float4*)&msrc[28];
            p0.x = pack_bf2(v4.x, v4.y); p0.y = pack_bf2(v4.z, v4.w);
            p0.z = pack_bf2(v5.x, v5.y); p0.w = pack_bf2(v5.z, v5.w);
            p1.x = pack_bf2(v6.x, v6.y); p1.y = pack_bf2(v6.z, v6.w);
            p1.z = pack_bf2(v7.x, v7.y); p1.w = pack_bf2(v7.z, v7.w);
            *(uint4*)&Mb[mr * 36 + mh / 2 + 8]  = p0;
            *(uint4*)&Mb[mr * 36 + mh / 2 + 12] = p1;
        }
        __syncthreads();

        // ---- S = (Q/8) K^T  (8 independent chains) ----
        float S[8][4];
        #pragma unroll
        for (int nt = 0; nt < 8; nt++) {
            S[nt][0] = S[nt][1] = S[nt][2] = S[nt][3] = 0.f;
            #pragma unroll
            for (int kc = 0; kc < 4; kc++) {
                int base = (nt * 8 + g) * 36 + kc * 8 + tg;
                unsigned b0h = KsHi[base], b1h = KsHi[base + 4];
                unsigned b0l = KsLo[base], b1l = KsLo[base + 4];
                MMA_BF16(S[nt], qhi[kc], b0h, b1h);
                MMA_BF16(S[nt], qhi[kc], b0l, b1l);
                MMA_BF16(S[nt], qlo[kc], b0h, b1h);
            }
        }

        // ---- mask (from smem) + dw + exp ----
        const float* dr = dwb + kt * 64;
        const int mrow0 = wid * 16 + g;
        #pragma unroll
        for (int nt = 0; nt < 8; nt++) {
            unsigned mp0 = Mb[mrow0 * 36 + nt * 4 + tg];
            unsigned mp1 = Mb[(mrow0 + 8) * 36 + nt * 4 + tg];
            float2 dv = *(const float2*)&dr[nt * 8 + 2 * tg];
            float m00 = __uint_as_float(mp0 << 16);
            float m01 = __uint_as_float(mp0 & 0xFFFF0000u);
            float m10 = __uint_as_float(mp1 << 16);
            float m11 = __uint_as_float(mp1 & 0xFFFF0000u);
            float p0 = __expf((S[nt][0] + (1.f - m00) * NEGBIG) * dv.x);
            float p1 = __expf((S[nt][1] + (1.f - m01) * NEGBIG) * dv.y);
            float p2 = __expf((S[nt][2] + (1.f - m10) * NEGBIG) * dv.x);
            float p3 = __expf((S[nt][3] + (1.f - m11) * NEGBIG) * dv.y);
            li0 += p0 + p1;
            li1 += p2 + p3;
            S[nt][0] = p0; S[nt][1] = p1; S[nt][2] = p2; S[nt][3] = p3;
        }

        // ---- O += P V ----
        #pragma unroll
        for (int kc = 0; kc < 4; kc++) {
            unsigned pa_h[4], pa_l[4];
            #pragma unroll
            for (int j = 0; j < 4; j++) {
                float x = S[2 * kc + (j >> 1)][(j & 1) ? 2 : 0];
                float y = S[2 * kc + (j >> 1)][(j & 1) ? 3 : 1];
                float hx = bf16_hi_f(x), hy = bf16_hi_f(y);
                pa_h[j] = pack_bf2(hx, hy);
                pa_l[j] = pack_bf2(x - hx, y - hy);
            }
            #pragma unroll
            for (int nt = 0; nt < 8; nt++) {
                int base = (nt * 8 + g) * 40 + kc * 8 + tg;
                unsigned b0h = VtHi[base], b1h = VtHi[base + 4];
                unsigned b0l = VtLo[base], b1l = VtLo[base + 4];
                MMA_BF16(O[nt], pa_h, b0h, b1h);
                MMA_BF16(O[nt], pa_h, b0l, b1l);
                MMA_BF16(O[nt], pa_l, b0h, b1h);
            }
        }
    }

    // ---- single li reduction over the 4 tg lanes ----
    #pragma unroll
    for (int off = 1; off <= 2; off <<= 1) {
        li0 += __shfl_xor_sync(0xffffffffu, li0, off);
        li1 += __shfl_xor_sync(0xffffffffu, li1, off);
    }

    // ---- epilogue: normalize and write ctx ----
    float inv0 = 1.f / li0, inv1 = 1.f / li1;
    #pragma unroll
    for (int nt = 0; nt < 8; nt++) {
        float2 r0, r1;
        r0.x = O[nt][0] * inv0; r0.y = O[nt][1] * inv0;
        r1.x = O[nt][2] * inv1; r1.y = O[nt][3] * inv1;
        *(float2*)&g_ctx[(size_t)(b * 1024 + qrow0 + g) * 512
                         + h * 64 + nt * 8 + 2 * tg] = r0;
        *(float2*)&g_ctx[(size_t)(b * 1024 + qrow0 + g + 8) * 512
                         + h * 64 + nt * 8 + 2 * tg] = r1;
    }
}

// ---------------------------------------------------------------------------
// Kernel 3: output projection.  A (ctx) staged pre-split in smem (NEW).
// grid = (64 mtiles, 4 ntiles), block = 256.  K=512, 16 chunks.
// ---------------------------------------------------------------------------
__global__ __launch_bounds__(256, 2) void oproj_kernel(
    const float* __restrict__ Wo,
    const float* __restrict__ bo,
    float* __restrict__ out)
{
    __shared__ __align__(16) unsigned Ahi[128 * 20];
    __shared__ __align__(16) unsigned Alo[128 * 20];
    __shared__ __align__(16) unsigned Whi[16 * 72];
    __shared__ __align__(16) unsigned Wlo[16 * 72];

    const int tid  = threadIdx.x;
    const int wid  = tid >> 5;
    const int lane = tid & 31;
    const int g    = lane >> 2;
    const int tg   = lane & 3;
    const int mt = blockIdx.x;
    const int noff = blockIdx.y * 64;

    const int ar = tid >> 1;
    const int ac = (tid & 1) * 16;
    const int kp = tid >> 4;
    const int n4 = (tid & 15) * 4;
    const int arow = wid * 16 + g;

    float C[8][4];
    #pragma unroll
    for (int nt = 0; nt < 8; nt++)
        #pragma unroll
        for (int j = 0; j < 4; j++) C[nt][j] = 0.f;

    for (int k0 = 0; k0 < 512; k0 += 32) {
        __syncthreads();
        {
            const float* asrc = &g_ctx[(size_t)(mt * 128 + ar) * 512 + k0 + ac];
            float4 v0 = *(const float4*)&asrc[0];
            float4 v1 = *(const float4*)&asrc[4];
            float4 v2 = *(const float4*)&asrc[8];
            float4 v3 = *(const float4*)&asrc[12];
            uint4 h4a, l4a, h4b, l4b;
            split4(v0, h4a.x, h4a.y, l4a.x, l4a.y);
            split4(v1, h4a.z, h4a.w, l4a.z, l4a.w);
            split4(v2, h4b.x, h4b.y, l4b.x, l4b.y);
            split4(v3, h4b.z, h4b.w, l4b.z, l4b.w);
            *(uint4*)&Ahi[ar * 20 + ac / 2]     = h4a;
            *(uint4*)&Ahi[ar * 20 + ac / 2 + 4] = h4b;
            *(uint4*)&Alo[ar * 20 + ac / 2]     = l4a;
            *(uint4*)&Alo[ar * 20 + ac / 2 + 4] = l4b;
        }
        {
            const float* wr0 = &Wo[(size_t)(k0 + 2 * kp) * 256 + noff + n4];
            const float* wr1 = wr0 + 256;
            float4 w0 = *(const float4*)wr0;
            float4 w1 = *(const float4*)wr1;
            float h0x = bf16_hi_f(w0.x), h1x = bf16_hi_f(w1.x);
            float h0y = bf16_hi_f(w0.y), h1y = bf16_hi_f(w1.y);
            float h0z = bf16_hi_f(w0.z), h1z = bf16_hi_f(w1.z);
            float h0w = bf16_hi_f(w0.w), h1w = bf16_hi_f(w1.w);
            uint4 hi4, lo4;
            hi4.x = pack_bf2(h0x, h1x);
            hi4.y = pack_bf2(h0y, h1y);
            hi4.z = pack_bf2(h0z, h1z);
            hi4.w = pack_bf2(h0w, h1w);
            lo4.x = pack_bf2(w0.x - h0x, w1.x - h1x);
            lo4.y = pack_bf2(w0.y - h0y, w1.y - h1y);
            lo4.z = pack_bf2(w0.z - h0z, w1.z - h1z);
            lo4.w = pack_bf2(w0.w - h0w, w1.w - h1w);
            *(uint4*)&Whi[kp * 72 + n4] = hi4;
            *(uint4*)&Wlo[kp * 72 + n4] = lo4;
        }
        __syncthreads();

        #pragma unroll
        for (int kc = 0; kc < 2; kc++) {
            unsigned ahi[4], alo[4];
            {
                int c0 = kc * 8 + tg;
                ahi[0] = Ahi[arow * 20 + c0];
                ahi[1] = Ahi[(arow + 8) * 20 + c0];
                ahi[2] = Ahi[arow * 20 + c0 + 4];
                ahi[3] = Ahi[(arow + 8) * 20 + c0 + 4];
                alo[0] = Alo[arow * 20 + c0];
                alo[1] = Alo[(arow + 8) * 20 + c0];
                alo[2] = Alo[arow * 20 + c0 + 4];
                alo[3] = Alo[(arow + 8) * 20 + c0 + 4];
            }
            #pragma unroll
            for (int nt = 0; nt < 8; nt++) {
                int base = (kc * 8 + tg) * 72 + nt * 8 + g;
                unsigned b0h = Whi[base], b1h = Whi[base + 4 * 72];
                unsigned b0l = Wlo[base], b1l = Wlo[base + 4 * 72];
                MMA_BF16(C[nt], ahi, b0h, b1h);
                MMA_BF16(C[nt], ahi, b0l, b1l);
                MMA_BF16(C[nt], alo, b0h, b1h);
            }
        }
    }

    #pragma unroll
    for (int nt = 0; nt < 8; nt++) {
        float2 bv = *(const float2*)&bo[noff + nt * 8 + 2 * tg];
        int m0 = mt * 128 + wid * 16 + g;
        float2 r0, r1;
        r0.x = C[nt][0] + bv.x; r0.y = C[nt][1] + bv.y;
        r1.x = C[nt][2] + bv.x; r1.y = C[nt][3] + bv.y;
        *(float2*)&out[(size_t)m0 * 256 + noff + nt * 8 + 2 * tg] = r0;
        *(float2*)&out[(size_t)(m0 + 8) * 256 + noff + nt * 8 + 2 * tg] = r1;
    }
}

// ---------------------------------------------------------------------------
extern "C" void kernel_launch(void* const* d_in, const int* in_sizes, int n_in,
                              void* d_out, int out_size)
{
    const float* X  = (const float*)d_in[0];
    const float* em = (const float*)d_in[1];
    const float* dw = (const float*)d_in[2];
    const float* Wq = (const float*)d_in[3];
    const float* Wk = (const float*)d_in[4];
    const float* Wv = (const float*)d_in[5];
    const float* Wo = (const float*)d_in[6];
    const float* bo = (const float*)d_in[7];
    float* out = (float*)d_out;

    cudaFuncSetAttribute(attn_kernel,
                         cudaFuncAttributeMaxDynamicSharedMemorySize,
                         ATTN_SMEM_BYTES);

    qkv_kernel  <<<dim3(64, 8, 3), 256>>>(X, Wq, Wk, Wv);
    attn_kernel <<<dim3(8, 8, 8), 256, ATTN_SMEM_BYTES>>>(em, dw);
    oproj_kernel<<<dim3(64, 4, 1), 256>>>(Wo, bo, out);
}

// round 16
// speedup vs baseline: 1.8331x; 1.8331x over previous
#include <cuda_runtime.h>
#include <cuda_bf16.h>
#include <math.h>

// ---------------------------------------------------------------------------
// CrystalGraphAttention  (B=8, N=1024, D=256, H=8, dk=dv=64)
//
//   q,k,v = X @ W{q,k,v}   (kernel 1, bf16 3-term; 2-stage W staging) [R12]
//   flash attention        (kernel 2, bf16 3-term; NO-MAX softmax;
//                           R15: double-buffered K/V smem -> ONE sync/tile)
//   out = ctx @ Wo + bo    (kernel 3, bf16 3-term; 4-stage W staging) [R12]
// ---------------------------------------------------------------------------

#define NEGBIG (-1.0e9f)

static __device__ float g_q [8 * 8 * 1024 * 64];    // [B,H,N,64]
static __device__ float g_k [8 * 8 * 1024 * 64];
static __device__ float g_v [8 * 8 * 1024 * 64];
static __device__ float g_ctx[8 * 1024 * 512];      // [B*N, H*64]

// ---------------------------------------------------------------------------
#define MMA_BF16(c, a, b0, b1)                                              \
    asm volatile(                                                           \
        "mma.sync.aligned.m16n8k16.row.col.f32.bf16.bf16.f32 "              \
        "{%0,%1,%2,%3}, {%4,%5,%6,%7}, {%8,%9}, {%0,%1,%2,%3};"             \
        : "+f"((c)[0]), "+f"((c)[1]), "+f"((c)[2]), "+f"((c)[3])            \
        : "r"((a)[0]), "r"((a)[1]), "r"((a)[2]), "r"((a)[3]),               \
          "r"(b0), "r"(b1))

__device__ __forceinline__ unsigned pack_bf2(float x, float y)
{
    unsigned r;
    asm("cvt.rn.bf16x2.f32 %0, %1, %2;" : "=r"(r) : "f"(y), "f"(x));
    return r;
}

__device__ __forceinline__ float bf16_hi_f(float x)
{
    return __bfloat162float(__float2bfloat16(x));
}

// ---------------------------------------------------------------------------
// Kernel 1: QKV projection (R12 measured-best, ~81us).
// ---------------------------------------------------------------------------
__global__ __launch_bounds__(256, 2) void qkv_kernel(
    const float* __restrict__ X,
    const float* __restrict__ Wq,
    const float* __restrict__ Wk,
    const float* __restrict__ Wv)
{
    __shared__ __align__(16) unsigned Whi[64 * 72];
    __shared__ __align__(16) unsigned Wlo[64 * 72];

    const int tid  = threadIdx.x;
    const int wid  = tid >> 5;
    const int lane = tid & 31;
    const int g    = lane >> 2;
    const int tg   = lane & 3;
    const int mt = blockIdx.x, h = blockIdx.y, w = blockIdx.z;
    const float* W = (w == 0) ? Wq : (w == 1) ? Wk : Wv;
    float* Out     = (w == 0) ? g_q : (w == 1) ? g_k : g_v;

    const int mrow0 = mt * 128 + wid * 16;
    const float* arow0 = &X[(size_t)(mrow0 + g) * 256];
    const float* arow1 = arow0 + 8 * 256;

    const int kp  = tid >> 2;
    const int n16 = (tid & 3) * 16;

    float C[8][4];
    #pragma unroll
    for (int nt = 0; nt < 8; nt++)
        #pragma unroll
        for (int j = 0; j < 4; j++) C[nt][j] = 0.f;

    #pragma unroll
    for (int s = 0; s < 2; s++) {
        __syncthreads();
        {
            const float* wr0 = &W[(size_t)(s * 128 + 2 * kp) * 512 + h * 64 + n16];
            const float* wr1 = wr0 + 512;
            #pragma unroll
            for (int c = 0; c < 16; c += 4) {
                float4 w0 = *(const float4*)&wr0[c];
                float4 w1 = *(const float4*)&wr1[c];
                float h0x = bf16_hi_f(w0.x), h1x = bf16_hi_f(w1.x);
                float h0y = bf16_hi_f(w0.y), h1y = bf16_hi_f(w1.y);
                float h0z = bf16_hi_f(w0.z), h1z = bf16_hi_f(w1.z);
                float h0w = bf16_hi_f(w0.w), h1w = bf16_hi_f(w1.w);
                uint4 hi4, lo4;
                hi4.x = pack_bf2(h0x, h1x);
                hi4.y = pack_bf2(h0y, h1y);
                hi4.z = pack_bf2(h0z, h1z);
                hi4.w = pack_bf2(h0w, h1w);
                lo4.x = pack_bf2(w0.x - h0x, w1.x - h1x);
                lo4.y = pack_bf2(w0.y - h0y, w1.y - h1y);
                lo4.z = pack_bf2(w0.z - h0z, w1.z - h1z);
                lo4.w = pack_bf2(w0.w - h0w, w1.w - h1w);
                *(uint4*)&Whi[kp * 72 + n16 + c] = hi4;
                *(uint4*)&Wlo[kp * 72 + n16 + c] = lo4;
            }
        }
        __syncthreads();

        #pragma unroll
        for (int k0 = 0; k0 < 128; k0 += 32) {
            #pragma unroll
            for (int kc = 0; kc < 2; kc++) {
                unsigned ahi[4], alo[4];
                {
                    int col = s * 128 + k0 + kc * 16 + 2 * tg;
                    float2 a0 = *(const float2*)&arow0[col];
                    float2 a1 = *(const float2*)&arow1[col];
                    float2 a2 = *(const float2*)&arow0[col + 8];
                    float2 a3 = *(const float2*)&arow1[col + 8];
                    float hx, hy;
                    hx = bf16_hi_f(a0.x); hy = bf16_hi_f(a0.y);
                    ahi[0] = pack_bf2(hx, hy); alo[0] = pack_bf2(a0.x - hx, a0.y - hy);
                    hx = bf16_hi_f(a1.x); hy = bf16_hi_f(a1.y);
                    ahi[1] = pack_bf2(hx, hy); alo[1] = pack_bf2(a1.x - hx, a1.y - hy);
                    hx = bf16_hi_f(a2.x); hy = bf16_hi_f(a2.y);
                    ahi[2] = pack_bf2(hx, hy); alo[2] = pack_bf2(a2.x - hx, a2.y - hy);
                    hx = bf16_hi_f(a3.x); hy = bf16_hi_f(a3.y);
                    ahi[3] = pack_bf2(hx, hy); alo[3] = pack_bf2(a3.x - hx, a3.y - hy);
                }
                #pragma unroll
                for (int nt = 0; nt < 8; nt++) {
                    int base = (k0 / 2 + kc * 8 + tg) * 72 + nt * 8 + g;
                    unsigned b0h = Whi[base], b1h = Whi[base + 4 * 72];
                    unsigned b0l = Wlo[base], b1l = Wlo[base + 4 * 72];
                    MMA_BF16(C[nt], ahi, b0h, b1h);
                    MMA_BF16(C[nt], ahi, b0l, b1l);
                    MMA_BF16(C[nt], alo, b0h, b1h);
                }
            }
        }
    }

    #pragma unroll
    for (int nt = 0; nt < 8; nt++) {
        int m0 = mrow0 + g;
        int m1 = m0 + 8;
        int b0i = m0 >> 10, s0 = m0 & 1023;
        int b1i = m1 >> 10, s1 = m1 & 1023;
        float2 r0, r1;
        r0.x = C[nt][0]; r0.y = C[nt][1];
        r1.x = C[nt][2]; r1.y = C[nt][3];
        *(float2*)&Out[(size_t)((b0i * 8 + h) * 1024 + s0) * 64 + nt * 8 + 2 * tg] = r0;
        *(float2*)&Out[(size_t)((b1i * 8 + h) * 1024 + s1) * 64 + nt * 8 + 2 * tg] = r1;
    }
}

// ---------------------------------------------------------------------------
// Kernel 2: flash attention, bf16 3-term, NO-MAX softmax.
// R15: double-buffered K/V smem tiles (dynamic, 2 x 38912 B) -> one sync/tile.
// Buffer safety: a warp staging buf[kt&1] at tile kt has passed the sync at
// tile kt-1, which guarantees all warps finished compute of tile kt-2 (the
// previous reader of this buffer).
// grid = (8 qtiles, 8 heads, 8 batches), block = 256 (8 warps).
// ---------------------------------------------------------------------------
#define AB_KHI 0
#define AB_KLO 2304
#define AB_VHI 4608
#define AB_VLO 7168
#define AB_STRIDE 9728
#define ATTN_SMEM_BYTES (2 * AB_STRIDE * 4)

__global__ __launch_bounds__(256, 2) void attn_kernel(
    const float* __restrict__ em,     // [B,1,N,N]
    const float* __restrict__ dw)     // [B,N]
{
    extern __shared__ __align__(16) unsigned sm[];

    const int tid  = threadIdx.x;
    const int wid  = tid >> 5;
    const int lane = tid & 31;
    const int g    = lane >> 2;
    const int tg   = lane & 3;
    const int qt = blockIdx.x, h = blockIdx.y, b = blockIdx.z;
    const int qrow0 = qt * 128 + wid * 16;

    const float* qb = &g_q[(size_t)((b * 8 + h) * 1024 + qrow0) * 64];
    const float* kb = &g_k[(size_t)(b * 8 + h) * 1024 * 64];
    const float* vb = &g_v[(size_t)(b * 8 + h) * 1024 * 64];
    const float* emb = em + (size_t)b * 1024 * 1024;
    const float* dwb = dw + b * 1024;

    // ---- Q fragments (scaled 1/8), packed bf16x2 hi/lo, resident ----
    unsigned qhi[4][4], qlo[4][4];
    #pragma unroll
    for (int kc = 0; kc < 4; kc++) {
        #pragma unroll
        for (int j = 0; j < 4; j++) {
            int row = (j & 1) ? g + 8 : g;
            int col = kc * 16 + 2 * tg + ((j >> 1) ? 8 : 0);
            float2 qv = *(const float2*)&qb[(size_t)row * 64 + col];
            qv.x *= 0.125f; qv.y *= 0.125f;
            float hx = bf16_hi_f(qv.x), hy = bf16_hi_f(qv.y);
            qhi[kc][j] = pack_bf2(hx, hy);
            qlo[kc][j] = pack_bf2(qv.x - hx, qv.y - hy);
        }
    }

    float O[8][4];
    #pragma unroll
    for (int nt = 0; nt < 8; nt++)
        #pragma unroll
        for (int j = 0; j < 4; j++) O[nt][j] = 0.f;
    float li0 = 0.f, li1 = 0.f;

    // staging maps
    const int kr  = tid >> 4;            // K: key row base (0..15)
    const int kc4 = (tid & 15) * 4;      // K: d base
    const int vkp = tid & 31;            // V: keypair (0..31)
    const int vd0 = (tid >> 5) * 8;      // V: d group base

    for (int kt = 0; kt < 16; kt++) {
        unsigned* buf  = sm + (kt & 1) * AB_STRIDE;
        unsigned* KsHi = buf + AB_KHI;   // [key][dpair]  stride 36
        unsigned* KsLo = buf + AB_KLO;
        unsigned* VtHi = buf + AB_VHI;   // [d][keypair]  stride 40
        unsigned* VtLo = buf + AB_VLO;

        // ---- stage K (hi/lo, [key][dpair]) ----
        {
            int r = kr;
            #pragma unroll
            for (int t = 0; t < 4; t++, r += 16) {
                float4 kv = *(const float4*)&kb[(size_t)(kt * 64 + r) * 64 + kc4];
                float h0 = bf16_hi_f(kv.x), h1 = bf16_hi_f(kv.y);
                float h2 = bf16_hi_f(kv.z), h3 = bf16_hi_f(kv.w);
                uint2 hp, lp;
                hp.x = pack_bf2(h0, h1);          hp.y = pack_bf2(h2, h3);
                lp.x = pack_bf2(kv.x - h0, kv.y - h1);
                lp.y = pack_bf2(kv.z - h2, kv.w - h3);
                *(uint2*)&KsHi[r * 36 + kc4 / 2] = hp;
                *(uint2*)&KsLo[r * 36 + kc4 / 2] = lp;
            }
        }
        // ---- stage V transposed (hi/lo, [d][keypair]) ----
        {
            const float* vr0 = &vb[(size_t)(kt * 64 + 2 * vkp) * 64 + vd0];
            const float* vr1 = vr0 + 64;
            float e0[8], e1[8];
            float4 t0 = *(const float4*)&vr0[0];
            float4 t1 = *(const float4*)&vr0[4];
            float4 u0 = *(const float4*)&vr1[0];
            float4 u1 = *(const float4*)&vr1[4];
            e0[0]=t0.x; e0[1]=t0.y; e0[2]=t0.z; e0[3]=t0.w;
            e0[4]=t1.x; e0[5]=t1.y; e0[6]=t1.z; e0[7]=t1.w;
            e1[0]=u0.x; e1[1]=u0.y; e1[2]=u0.z; e1[3]=u0.w;
            e1[4]=u1.x; e1[5]=u1.y; e1[6]=u1.z; e1[7]=u1.w;
            #pragma unroll
            for (int i = 0; i < 8; i++) {
                float h0 = bf16_hi_f(e0[i]), h1 = bf16_hi_f(e1[i]);
                VtHi[(vd0 + i) * 40 + vkp] = pack_bf2(h0, h1);
                VtLo[(vd0 + i) * 40 + vkp] = pack_bf2(e0[i] - h0, e1[i] - h1);
            }
        }
        __syncthreads();   // the ONLY barrier per tile

        // ---- S = (Q/8) K^T  (8 independent MMA chains) ----
        float S[8][4];
        #pragma unroll
        for (int nt = 0; nt < 8; nt++) {
            S[nt][0] = S[nt][1] = S[nt][2] = S[nt][3] = 0.f;
            #pragma unroll
            for (int kc = 0; kc < 4; kc++) {
                int base = (nt * 8 + g) * 36 + kc * 8 + tg;
                unsigned b0h = KsHi[base], b1h = KsHi[base + 4];
                unsigned b0l = KsLo[base], b1l = KsLo[base + 4];
                MMA_BF16(S[nt], qhi[kc], b0h, b1h);
                MMA_BF16(S[nt], qhi[kc], b0l, b1l);
                MMA_BF16(S[nt], qlo[kc], b0h, b1h);
            }
        }

        // ---- mask + dw + exp (no max, no shuffles) ----
        const float* er0 = emb + (size_t)(qrow0 + g) * 1024 + kt * 64;
        const float* er1 = er0 + (size_t)8 * 1024;
        const float* dr  = dwb + kt * 64;
        #pragma unroll
        for (int nt = 0; nt < 8; nt++) {
            float2 m0v = *(const float2*)&er0[nt * 8 + 2 * tg];
            float2 m1v = *(const float2*)&er1[nt * 8 + 2 * tg];
            float2 dv  = *(const float2*)&dr [nt * 8 + 2 * tg];
            float p0 = __expf((S[nt][0] + (1.f - m0v.x) * NEGBIG) * dv.x);
            float p1 = __expf((S[nt][1] + (1.f - m0v.y) * NEGBIG) * dv.y);
            float p2 = __expf((S[nt][2] + (1.f - m1v.x) * NEGBIG) * dv.x);
            float p3 = __expf((S[nt][3] + (1.f - m1v.y) * NEGBIG) * dv.y);
            li0 += p0 + p1;
            li1 += p2 + p3;
            S[nt][0] = p0; S[nt][1] = p1; S[nt][2] = p2; S[nt][3] = p3;
        }

        // ---- O += P V  (P A-frags from S registers) ----
        #pragma unroll
        for (int kc = 0; kc < 4; kc++) {
            unsigned pa_h[4], pa_l[4];
            #pragma unroll
            for (int j = 0; j < 4; j++) {
                float x = S[2 * kc + (j >> 1)][(j & 1) ? 2 : 0];
                float y = S[2 * kc + (j >> 1)][(j & 1) ? 3 : 1];
                float hx = bf16_hi_f(x), hy = bf16_hi_f(y);
                pa_h[j] = pack_bf2(hx, hy);
                pa_l[j] = pack_bf2(x - hx, y - hy);
            }
            #pragma unroll
            for (int nt = 0; nt < 8; nt++) {
                int base = (nt * 8 + g) * 40 + kc * 8 + tg;
                unsigned b0h = VtHi[base], b1h = VtHi[base + 4];
                unsigned b0l = VtLo[base], b1l = VtLo[base + 4];
                MMA_BF16(O[nt], pa_h, b0h, b1h);
                MMA_BF16(O[nt], pa_h, b0l, b1l);
                MMA_BF16(O[nt], pa_l, b0h, b1h);
            }
        }
    }

    // ---- single li reduction over the 4 tg lanes ----
    #pragma unroll
    for (int off = 1; off <= 2; off <<= 1) {
        li0 += __shfl_xor_sync(0xffffffffu, li0, off);
        li1 += __shfl_xor_sync(0xffffffffu, li1, off);
    }

    // ---- epilogue: normalize and write ctx ----
    float inv0 = 1.f / li0, inv1 = 1.f / li1;
    #pragma unroll
    for (int nt = 0; nt < 8; nt++) {
        float2 r0, r1;
        r0.x = O[nt][0] * inv0; r0.y = O[nt][1] * inv0;
        r1.x = O[nt][2] * inv1; r1.y = O[nt][3] * inv1;
        *(float2*)&g_ctx[(size_t)(b * 1024 + qrow0 + g) * 512
                         + h * 64 + nt * 8 + 2 * tg] = r0;
        *(float2*)&g_ctx[(size_t)(b * 1024 + qrow0 + g + 8) * 512
                         + h * 64 + nt * 8 + 2 * tg] = r1;
    }
}

// ---------------------------------------------------------------------------
// Kernel 3: output projection (R12 version).
// ---------------------------------------------------------------------------
__global__ __launch_bounds__(256, 2) void oproj_kernel(
    const float* __restrict__ Wo,
    const float* __restrict__ bo,
    float* __restrict__ out)
{
    __shared__ __align__(16) unsigned Whi[64 * 72];
    __shared__ __align__(16) unsigned Wlo[64 * 72];

    const int tid  = threadIdx.x;
    const int wid  = tid >> 5;
    const int lane = tid & 31;
    const int g    = lane >> 2;
    const int tg   = lane & 3;
    const int mt = blockIdx.x;
    const int noff = blockIdx.y * 64;

    const int mrow0 = mt * 128 + wid * 16;
    const float* arow0 = &g_ctx[(size_t)(mrow0 + g) * 512];
    const float* arow1 = arow0 + 8 * 512;

    const int kp  = tid >> 2;
    const int n16 = (tid & 3) * 16;

    float C[8][4];
    #pragma unroll
    for (int nt = 0; nt < 8; nt++)
        #pragma unroll
        for (int j = 0; j < 4; j++) C[nt][j] = 0.f;

    #pragma unroll
    for (int s = 0; s < 4; s++) {
        __syncthreads();
        {
            const float* wr0 = &Wo[(size_t)(s * 128 + 2 * kp) * 256 + noff + n16];
            const float* wr1 = wr0 + 256;
            #pragma unroll
            for (int c = 0; c < 16; c += 4) {
                float4 w0 = *(const float4*)&wr0[c];
                float4 w1 = *(const float4*)&wr1[c];
                float h0x = bf16_hi_f(w0.x), h1x = bf16_hi_f(w1.x);
                float h0y = bf16_hi_f(w0.y), h1y = bf16_hi_f(w1.y);
                float h0z = bf16_hi_f(w0.z), h1z = bf16_hi_f(w1.z);
                float h0w = bf16_hi_f(w0.w), h1w = bf16_hi_f(w1.w);
                uint4 hi4, lo4;
                hi4.x = pack_bf2(h0x, h1x);
                hi4.y = pack_bf2(h0y, h1y);
                hi4.z = pack_bf2(h0z, h1z);
                hi4.w = pack_bf2(h0w, h1w);
                lo4.x = pack_bf2(w0.x - h0x, w1.x - h1x);
                lo4.y = pack_bf2(w0.y - h0y, w1.y - h1y);
                lo4.z = pack_bf2(w0.z - h0z, w1.z - h1z);
                lo4.w = pack_bf2(w0.w - h0w, w1.w - h1w);
                *(uint4*)&Whi[kp * 72 + n16 + c] = hi4;
                *(uint4*)&Wlo[kp * 72 + n16 + c] = lo4;
            }
        }
        __syncthreads();

        #pragma unroll
        for (int k0 = 0; k0 < 128; k0 += 32) {
            #pragma unroll
            for (int kc = 0; kc < 2; kc++) {
                unsigned ahi[4], alo[4];
                {
                    int col = s * 128 + k0 + kc * 16 + 2 * tg;
                    float2 a0 = *(const float2*)&arow0[col];
                    float2 a1 = *(const float2*)&arow1[col];
                    float2 a2 = *(const float2*)&arow0[col + 8];
                    float2 a3 = *(const float2*)&arow1[col + 8];
                    float hx, hy;
                    hx = bf16_hi_f(a0.x); hy = bf16_hi_f(a0.y);
                    ahi[0] = pack_bf2(hx, hy); alo[0] = pack_bf2(a0.x - hx, a0.y - hy);
                    hx = bf16_hi_f(a1.x); hy = bf16_hi_f(a1.y);
                    ahi[1] = pack_bf2(hx, hy); alo[1] = pack_bf2(a1.x - hx, a1.y - hy);
                    hx = bf16_hi_f(a2.x); hy = bf16_hi_f(a2.y);
                    ahi[2] = pack_bf2(hx, hy); alo[2] = pack_bf2(a2.x - hx, a2.y - hy);
                    hx = bf16_hi_f(a3.x); hy = bf16_hi_f(a3.y);
                    ahi[3] = pack_bf2(hx, hy); alo[3] = pack_bf2(a3.x - hx, a3.y - hy);
                }
                #pragma unroll
                for (int nt = 0; nt < 8; nt++) {
                    int base = (k0 / 2 + kc * 8 + tg) * 72 + nt * 8 + g;
                    unsigned b0h = Whi[base], b1h = Whi[base + 4 * 72];
                    unsigned b0l = Wlo[base], b1l = Wlo[base + 4 * 72];
                    MMA_BF16(C[nt], ahi, b0h, b1h);
                    MMA_BF16(C[nt], ahi, b0l, b1l);
                    MMA_BF16(C[nt], alo, b0h, b1h);
                }
            }
        }
    }

    #pragma unroll
    for (int nt = 0; nt < 8; nt++) {
        float2 bv = *(const float2*)&bo[noff + nt * 8 + 2 * tg];
        int m0 = mrow0 + g;
        float2 r0, r1;
        r0.x = C[nt][0] + bv.x; r0.y = C[nt][1] + bv.y;
        r1.x = C[nt][2] + bv.x; r1.y = C[nt][3] + bv.y;
        *(float2*)&out[(size_t)m0 * 256 + noff + nt * 8 + 2 * tg] = r0;
        *(float2*)&out[(size_t)(m0 + 8) * 256 + noff + nt * 8 + 2 * tg] = r1;
    }
}

// ---------------------------------------------------------------------------
extern "C" void kernel_launch(void* const* d_in, const int* in_sizes, int n_in,
                              void* d_out, int out_size)
{
    const float* X  = (const float*)d_in[0];
    const float* em = (const float*)d_in[1];
    const float* dw = (const float*)d_in[2];
    const float* Wq = (const float*)d_in[3];
    const float* Wk = (const float*)d_in[4];
    const float* Wv = (const float*)d_in[5];
    const float* Wo = (const float*)d_in[6];
    const float* bo = (const float*)d_in[7];
    float* out = (float*)d_out;

    cudaFuncSetAttribute(attn_kernel,
                         cudaFuncAttributeMaxDynamicSharedMemorySize,
                         ATTN_SMEM_BYTES);

    qkv_kernel  <<<dim3(64, 8, 3), 256>>>(X, Wq, Wk, Wv);
    attn_kernel <<<dim3(8, 8, 8), 256, ATTN_SMEM_BYTES>>>(em, dw);
    oproj_kernel<<<dim3(64, 4, 1), 256>>>(Wo, bo, out);
}